// round 8
// baseline (speedup 1.0000x reference)
#include <cuda_runtime.h>
#include <math.h>

#define TT   30
#define BB   32
#define VV   32
#define FF   128
#define LL   256
#define LFF  64
#define HH   8
#define DHH  16
#define HISTN 10
#define MROWS (TT*BB*VV)   // 30720

typedef unsigned long long u64;

// ---- packed f32x2 helpers (sm_100+ PTX; per-lane IEEE fp32 FMA) ----
__device__ __forceinline__ u64 pk2(float a, float b) {
    u64 r; asm("mov.b64 %0,{%1,%2};" : "=l"(r) : "f"(a), "f"(b)); return r;
}
__device__ __forceinline__ float2 up2(u64 v) {
    float2 f; asm("mov.b64 {%0,%1},%2;" : "=f"(f.x), "=f"(f.y) : "l"(v)); return f;
}
__device__ __forceinline__ void fma2(u64& d, u64 a, u64 b) {
    asm("fma.rn.f32x2 %0,%1,%2,%0;" : "+l"(d) : "l"(a), "l"(b));
}

// ---------------- scratch (no allocations allowed) ----------------
__device__ float g_Kproj[BB*LL*FF];     // lane keys   [B,L,F]
__device__ float g_LV[BB*LL*FF];        // logsig(lane values) [B,L,F]
__device__ unsigned char g_mask[BB*LL]; // any-over-HIST mask
__device__ float g_q[MROWS*FF];
__device__ float g_r[MROWS*FF];
__device__ float g_pre[MROWS*FF];       // (r*att) in [T,B,(h,v,d)] layout == raw reshape

// ---------------- lane projection ----------------
template<bool LOGSIG>
__global__ __launch_bounds__(256) void lane_proj_kernel(
    const float* __restrict__ lanes, const float* __restrict__ W,
    const float* __restrict__ bias, float* __restrict__ out)
{
    __shared__ float Wsh[LFF][FF + 1];
    __shared__ float lsh[32][LFF];
    __shared__ float bsh[FF];
    int tid = threadIdx.x;
    int row0 = blockIdx.x * 32;

    #pragma unroll
    for (int i = 0; i < 32; i++) {
        int idx = tid + i * 256;
        int f = idx >> 6, j = idx & 63;
        Wsh[j][f] = W[idx];
    }
    if (tid < FF) bsh[tid] = bias[tid];
    #pragma unroll
    for (int i = 0; i < 2; i++) {
        int idx = tid + i * 256;
        int r = idx >> 4;
        int c = (idx & 15) * 4;
        *(float4*)&lsh[r][c] = *(const float4*)(lanes + (size_t)(row0 + r) * LFF + c);
    }
    __syncthreads();

    int f = tid & 127;
    for (int r = tid >> 7; r < 32; r += 2) {
        float acc = bsh[f];
        #pragma unroll
        for (int j = 0; j < LFF; j++) acc += lsh[r][j] * Wsh[j][f];
        if (LOGSIG) {
            // log_sigmoid(x), numerically stable, fast intrinsics
            acc = (acc >= 0.f) ? -__logf(1.f + __expf(-acc))
                               : acc - __logf(1.f + __expf(acc));
        }
        out[(size_t)(row0 + r) * FF + f] = acc;
    }
}

// ---------------- mask: any over HIST, dtype self-detection ----------------
__global__ void mask_kernel(const unsigned char* __restrict__ m)
{
    int tid = threadIdx.x;
    const unsigned int* w = (const unsigned int*)m;
    bool okI = true, okF = true;
    for (int j = tid; j < (HISTN * BB * LL) / 4; j += 256) {
        unsigned int x = w[j];
        if (x > 1u) okI = false;
        if (x != 0u && x != 0x3F800000u) okF = false;
    }
    okI = __syncthreads_and((int)okI) != 0;
    okF = __syncthreads_and((int)okF) != 0;
    int cls = okI ? 0 : (okF ? 1 : 2);

    for (int i = tid; i < BB * LL; i += 256) {
        unsigned int any = 0;
        #pragma unroll
        for (int h = 0; h < HISTN; h++) {
            int j = h * BB * LL + i;
            unsigned int v;
            if (cls == 0)      v = w[j];
            else if (cls == 1) v = (w[j] != 0u);
            else               v = m[j];
            any |= v;
        }
        g_mask[i] = any ? 1 : 0;
    }
}

// ---------------- 30720x128x128 GEMM (packed f32x2): C = A@W^T + bias (+E1-E2) ----------------
template<bool SUM_AB, bool EPI>
__global__ __launch_bounds__(256) void gemm128_kernel(
    const float* __restrict__ A1, const float* __restrict__ A2,
    const float* __restrict__ W,  const float* __restrict__ bias,
    float* __restrict__ C,
    const float* __restrict__ E1, const float* __restrict__ E2)
{
    __shared__ float Ash[64][36];
    __shared__ float Wsh[32][132];
    int tid = threadIdx.x;
    int tx = tid & 31, ty = tid >> 5;
    int m0 = blockIdx.x * 64;

    u64 acc2[8][2];
    #pragma unroll
    for (int i = 0; i < 8; i++) { acc2[i][0] = 0ull; acc2[i][1] = 0ull; }

    for (int k0 = 0; k0 < 128; k0 += 32) {
        #pragma unroll
        for (int i = 0; i < 2; i++) {
            int idx = tid + i * 256;
            int row = idx >> 3, c = (idx & 7) * 4;
            float4 a = *(const float4*)(A1 + (size_t)(m0 + row) * FF + k0 + c);
            if (SUM_AB) {
                float4 b = *(const float4*)(A2 + (size_t)(m0 + row) * FF + k0 + c);
                a.x += b.x; a.y += b.y; a.z += b.z; a.w += b.w;
            }
            *(float4*)&Ash[row][c] = a;
        }
        #pragma unroll
        for (int i = 0; i < 16; i++) {
            int idx = tid + i * 256;
            int n = idx >> 5, kk = idx & 31;
            Wsh[kk][n] = W[n * FF + k0 + kk];
        }
        __syncthreads();
        #pragma unroll
        for (int k = 0; k < 32; k++) {
            ulonglong2 b2 = *(ulonglong2*)&Wsh[k][tx * 4];
            #pragma unroll
            for (int i = 0; i < 8; i++) {
                float a = Ash[ty * 8 + i][k];
                u64 a2 = pk2(a, a);
                fma2(acc2[i][0], a2, b2.x);
                fma2(acc2[i][1], a2, b2.y);
            }
        }
        __syncthreads();
    }

    int n = tx * 4;
    float4 bb = *(const float4*)(bias + n);
    #pragma unroll
    for (int i = 0; i < 8; i++) {
        int m = m0 + ty * 8 + i;
        float2 lo = up2(acc2[i][0]), hi = up2(acc2[i][1]);
        float4 o;
        o.x = lo.x + bb.x; o.y = lo.y + bb.y;
        o.z = hi.x + bb.z; o.w = hi.y + bb.w;
        if (EPI) {
            float4 e1 = *(const float4*)(E1 + (size_t)m * FF + n);
            float4 e2 = *(const float4*)(E2 + (size_t)m * FF + n);
            o.x += e1.x - e2.x; o.y += e1.y - e2.y;
            o.z += e1.z - e2.z; o.w += e1.w - e2.w;
        }
        *(float4*)(C + (size_t)m * FF + n) = o;
    }
}

// ---------------- fused q+r GEMM (packed f32x2) ----------------
__global__ __launch_bounds__(256, 2) void gemm_qr_kernel(
    const float* __restrict__ A1, const float* __restrict__ A2,
    const float* __restrict__ Wq, const float* __restrict__ bq,
    const float* __restrict__ Wr, const float* __restrict__ br,
    float* __restrict__ Cq, float* __restrict__ Cr)
{
    __shared__ float Ash[64][36];
    __shared__ float W1[32][132];
    __shared__ float W2[32][132];
    int tid = threadIdx.x;
    int tx = tid & 31, ty = tid >> 5;
    int m0 = blockIdx.x * 64;

    u64 aq[8][2], ar[8][2];
    #pragma unroll
    for (int i = 0; i < 8; i++) {
        aq[i][0] = aq[i][1] = 0ull;
        ar[i][0] = ar[i][1] = 0ull;
    }

    for (int k0 = 0; k0 < 128; k0 += 32) {
        #pragma unroll
        for (int i = 0; i < 2; i++) {
            int idx = tid + i * 256;
            int row = idx >> 3, c = (idx & 7) * 4;
            float4 a = *(const float4*)(A1 + (size_t)(m0 + row) * FF + k0 + c);
            float4 b = *(const float4*)(A2 + (size_t)(m0 + row) * FF + k0 + c);
            a.x += b.x; a.y += b.y; a.z += b.z; a.w += b.w;
            *(float4*)&Ash[row][c] = a;
        }
        #pragma unroll
        for (int i = 0; i < 16; i++) {
            int idx = tid + i * 256;
            int n = idx >> 5, kk = idx & 31;
            W1[kk][n] = Wq[n * FF + k0 + kk];
            W2[kk][n] = Wr[n * FF + k0 + kk];
        }
        __syncthreads();
        #pragma unroll
        for (int k = 0; k < 32; k++) {
            ulonglong2 q2 = *(ulonglong2*)&W1[k][tx * 4];
            ulonglong2 r2 = *(ulonglong2*)&W2[k][tx * 4];
            #pragma unroll
            for (int i = 0; i < 8; i++) {
                float a = Ash[ty * 8 + i][k];
                u64 a2 = pk2(a, a);
                fma2(aq[i][0], a2, q2.x);
                fma2(aq[i][1], a2, q2.y);
                fma2(ar[i][0], a2, r2.x);
                fma2(ar[i][1], a2, r2.y);
            }
        }
        __syncthreads();
    }

    int n = tx * 4;
    float4 bq4 = *(const float4*)(bq + n);
    float4 br4 = *(const float4*)(br + n);
    #pragma unroll
    for (int i = 0; i < 8; i++) {
        int m = m0 + ty * 8 + i;
        float2 qlo = up2(aq[i][0]), qhi = up2(aq[i][1]);
        float2 rlo = up2(ar[i][0]), rhi = up2(ar[i][1]);
        float4 oq, orr;
        oq.x  = qlo.x + bq4.x; oq.y  = qlo.y + bq4.y;
        oq.z  = qhi.x + bq4.z; oq.w  = qhi.y + bq4.w;
        orr.x = rlo.x + br4.x; orr.y = rlo.y + br4.y;
        orr.z = rhi.x + br4.z; orr.w = rhi.y + br4.w;
        *(float4*)(Cq + (size_t)m * FF + n) = oq;
        *(float4*)(Cr + (size_t)m * FF + n) = orr;
    }
}

// ---------------- attention v3: f32x2 + fast exp ----------------
#define TPB2 6
__global__ __launch_bounds__(256) void attn3_kernel()
{
    __shared__ float sc[32][260];       // scores -> unnormalized p (padded rows)
    __shared__ float lvsh[256][16];     // logsig(val) for this (b,h)
    __shared__ float qsh[32][16];
    __shared__ float sinv[32];
    __shared__ float pb[256][4];        // phase-B partials

    int tid = threadIdx.x;
    int b = blockIdx.x >> 3, h = blockIdx.x & 7;
    int t0 = blockIdx.y * TPB2;
    int l = tid;
    int warp = tid >> 5, lane = tid & 31;

    // K row for this l in packed registers (8 x f32x2)
    u64 k2[8];
    {
        const float* kp = g_Kproj + ((size_t)(b * LL + l)) * FF + h * DHH;
        ulonglong2 ka = *(const ulonglong2*)(kp);
        ulonglong2 kb = *(const ulonglong2*)(kp + 4);
        ulonglong2 kc = *(const ulonglong2*)(kp + 8);
        ulonglong2 kd = *(const ulonglong2*)(kp + 12);
        k2[0] = ka.x; k2[1] = ka.y; k2[2] = kb.x; k2[3] = kb.y;
        k2[4] = kc.x; k2[5] = kc.y; k2[6] = kd.x; k2[7] = kd.y;
        const float* lvp = g_LV + ((size_t)(b * LL + l)) * FF + h * DHH;
        #pragma unroll
        for (int i = 0; i < 4; i++)
            *(float4*)&lvsh[l][i * 4] = *(const float4*)(lvp + i * 4);
    }
    bool mon = g_mask[b * LL + l] != 0;

    // phase-B thread mapping
    int dq = tid & 3;            // d quad
    int half = (tid >> 2) & 1;   // contiguous l half
    int vB = tid >> 3;           // v row 0..31
    int lbase = half * 128;

    for (int t = t0; t < t0 + TPB2; t++) {
        __syncthreads();                 // protect qsh/sc/sinv reuse
        if (tid < 128) {                 // load q tile [32,16] as float4
            int v = tid >> 2, q4 = tid & 3;
            *(float4*)&qsh[v][q4 * 4] =
                *(const float4*)(g_q + ((size_t)((t * BB + b) * VV + v)) * FF + h * DHH + q4 * 4);
        }
        __syncthreads();

        // ---- Phase A: scores via packed FMA, thread l = column l ----
        #pragma unroll
        for (int v = 0; v < 32; v++) {
            ulonglong2 qa = *(const ulonglong2*)&qsh[v][0];
            ulonglong2 qb = *(const ulonglong2*)&qsh[v][4];
            ulonglong2 qc = *(const ulonglong2*)&qsh[v][8];
            ulonglong2 qd = *(const ulonglong2*)&qsh[v][12];
            u64 acc = 0ull;
            fma2(acc, k2[0], qa.x); fma2(acc, k2[1], qa.y);
            fma2(acc, k2[2], qb.x); fma2(acc, k2[3], qb.y);
            fma2(acc, k2[4], qc.x); fma2(acc, k2[5], qc.y);
            fma2(acc, k2[6], qd.x); fma2(acc, k2[7], qd.y);
            float2 s2 = up2(acc);
            float s = s2.x + s2.y;
            sc[v][l] = mon ? (s * 0.25f) : -1e9f;
        }
        __syncthreads();

        // ---- softmax over l, 4 rows per warp, fast exp ----
        #pragma unroll
        for (int rr = 0; rr < 4; rr++) {
            int rv = warp + rr * 8;
            float4 a = *(float4*)&sc[rv][lane * 8];
            float4 c = *(float4*)&sc[rv][lane * 8 + 4];
            float mx = fmaxf(fmaxf(fmaxf(a.x, a.y), fmaxf(a.z, a.w)),
                             fmaxf(fmaxf(c.x, c.y), fmaxf(c.z, c.w)));
            #pragma unroll
            for (int o = 16; o > 0; o >>= 1)
                mx = fmaxf(mx, __shfl_xor_sync(0xffffffffu, mx, o));
            a.x = __expf(a.x - mx); a.y = __expf(a.y - mx);
            a.z = __expf(a.z - mx); a.w = __expf(a.w - mx);
            c.x = __expf(c.x - mx); c.y = __expf(c.y - mx);
            c.z = __expf(c.z - mx); c.w = __expf(c.w - mx);
            float sm = a.x + a.y + a.z + a.w + c.x + c.y + c.z + c.w;
            #pragma unroll
            for (int o = 16; o > 0; o >>= 1)
                sm += __shfl_xor_sync(0xffffffffu, sm, o);
            *(float4*)&sc[rv][lane * 8] = a;
            *(float4*)&sc[rv][lane * 8 + 4] = c;
            if (lane == 0) sinv[rv] = __fdividef(1.f, sm);
        }
        __syncthreads();

        // ---- Phase B: contiguous half, 4-wide unroll, packed FMA ----
        {
            u64 acc0 = 0ull, acc1 = 0ull;
            #pragma unroll 8
            for (int g = 0; g < 32; g++) {
                int ll2 = lbase + g * 4;
                float4 p4 = *(float4*)&sc[vB][ll2];
                ulonglong2 lv;
                u64 pu;
                pu = pk2(p4.x, p4.x); lv = *(ulonglong2*)&lvsh[ll2 + 0][dq * 4];
                fma2(acc0, pu, lv.x); fma2(acc1, pu, lv.y);
                pu = pk2(p4.y, p4.y); lv = *(ulonglong2*)&lvsh[ll2 + 1][dq * 4];
                fma2(acc0, pu, lv.x); fma2(acc1, pu, lv.y);
                pu = pk2(p4.z, p4.z); lv = *(ulonglong2*)&lvsh[ll2 + 2][dq * 4];
                fma2(acc0, pu, lv.x); fma2(acc1, pu, lv.y);
                pu = pk2(p4.w, p4.w); lv = *(ulonglong2*)&lvsh[ll2 + 3][dq * 4];
                fma2(acc0, pu, lv.x); fma2(acc1, pu, lv.y);
            }
            float2 a01 = up2(acc0), a23 = up2(acc1);
            float4 acc = make_float4(a01.x, a01.y, a23.x, a23.y);
            *(float4*)&pb[tid][0] = acc;
            __syncthreads();
            if (half == 0) {
                float4 o = *(float4*)&pb[tid ^ 4][0];
                o.x += acc.x; o.y += acc.y; o.z += acc.z; o.w += acc.w;
                float si = sinv[vB];
                float4 r4 = *(const float4*)(g_r + ((size_t)((t * BB + b) * VV + vB)) * FF + h * DHH + dq * 4);
                float4 res;
                res.x = r4.x * __expf(o.x * si);
                res.y = r4.y * __expf(o.y * si);
                res.z = r4.z * __expf(o.z * si);
                res.w = r4.w * __expf(o.w * si);
                *(float4*)(g_pre + ((size_t)(t * BB + b)) * (VV * FF)
                           + h * (VV * DHH) + vB * DHH + dq * 4) = res;
            }
        }
    }
}

// ---------------- launch ----------------
extern "C" void kernel_launch(void* const* d_in, const int* in_sizes, int n_in,
                              void* d_out, int out_size)
{
    const float* vehicles    = (const float*)d_in[0];
    const float* initial_pos = (const float*)d_in[1];
    const float* lanes       = (const float*)d_in[2];
    const unsigned char* mask_lanes = (const unsigned char*)d_in[3];
    const float* Wk = (const float*)d_in[4];
    const float* bk = (const float*)d_in[5];
    const float* Wv = (const float*)d_in[6];
    const float* bv = (const float*)d_in[7];
    const float* Wq = (const float*)d_in[8];
    const float* bq = (const float*)d_in[9];
    const float* Wr = (const float*)d_in[10];
    const float* br = (const float*)d_in[11];
    const float* Wc = (const float*)d_in[12];
    const float* bc = (const float*)d_in[13];
    float* out = (float*)d_out;

    float *gK, *gLV, *gq, *gr, *gpre;
    cudaGetSymbolAddress((void**)&gK,   g_Kproj);
    cudaGetSymbolAddress((void**)&gLV,  g_LV);
    cudaGetSymbolAddress((void**)&gq,   g_q);
    cudaGetSymbolAddress((void**)&gr,   g_r);
    cudaGetSymbolAddress((void**)&gpre, g_pre);

    // 1) lane projections + mask
    lane_proj_kernel<false><<<BB * LL / 32, 256>>>(lanes, Wk, bk, gK);
    lane_proj_kernel<true ><<<BB * LL / 32, 256>>>(lanes, Wv, bv, gLV);
    mask_kernel<<<1, 256>>>(mask_lanes);

    // 2) fused q, r projections on v = vehicles + initial_pos
    gemm_qr_kernel<<<MROWS / 64, 256>>>(vehicles, initial_pos, Wq, bq, Wr, br, gq, gr);

    // 3) attention
    attn3_kernel<<<dim3(BB * HH, TT / TPB2), 256>>>();

    // 4) combine + residual: out = pre @ Wc^T + bc + vehicles - initial_pos
    gemm128_kernel<false, true><<<MROWS / 64, 256>>>(gpre, nullptr, Wc, bc, out, vehicles, initial_pos);
}

// round 9
// speedup vs baseline: 1.2204x; 1.2204x over previous
#include <cuda_runtime.h>
#include <math.h>

#define TT   30
#define BB   32
#define VV   32
#define FF   128
#define LL   256
#define LFF  64
#define HH   8
#define DHH  16
#define HISTN 10
#define MROWS (TT*BB*VV)   // 30720

typedef unsigned long long u64;

// ---- packed f32x2 helpers (sm_100+ PTX; per-lane IEEE fp32 FMA) ----
__device__ __forceinline__ u64 pk2(float a, float b) {
    u64 r; asm("mov.b64 %0,{%1,%2};" : "=l"(r) : "f"(a), "f"(b)); return r;
}
__device__ __forceinline__ float2 up2(u64 v) {
    float2 f; asm("mov.b64 {%0,%1},%2;" : "=f"(f.x), "=f"(f.y) : "l"(v)); return f;
}
__device__ __forceinline__ void fma2(u64& d, u64 a, u64 b) {
    asm("fma.rn.f32x2 %0,%1,%2,%0;" : "+l"(d) : "l"(a), "l"(b));
}

// ---------------- scratch (no allocations allowed) ----------------
__device__ float g_Kproj[BB*LL*FF];     // lane keys   [B,L,F]
__device__ float g_LV[BB*LL*FF];        // logsig(lane values) [B,L,F]
__device__ unsigned char g_mask[BB*LL]; // any-over-HIST mask
__device__ float g_q[MROWS*FF];
__device__ float g_r[MROWS*FF];
__device__ float g_pre[MROWS*FF];       // (r*att) in [T,B,(h,v,d)] layout == raw reshape

// ---------------- lane projection ----------------
template<bool LOGSIG>
__global__ __launch_bounds__(256) void lane_proj_kernel(
    const float* __restrict__ lanes, const float* __restrict__ W,
    const float* __restrict__ bias, float* __restrict__ out)
{
    __shared__ float Wsh[LFF][FF + 1];
    __shared__ float lsh[32][LFF];
    __shared__ float bsh[FF];
    int tid = threadIdx.x;
    int row0 = blockIdx.x * 32;

    #pragma unroll
    for (int i = 0; i < 32; i++) {
        int idx = tid + i * 256;
        int f = idx >> 6, j = idx & 63;
        Wsh[j][f] = W[idx];
    }
    if (tid < FF) bsh[tid] = bias[tid];
    #pragma unroll
    for (int i = 0; i < 2; i++) {
        int idx = tid + i * 256;
        int r = idx >> 4;
        int c = (idx & 15) * 4;
        *(float4*)&lsh[r][c] = *(const float4*)(lanes + (size_t)(row0 + r) * LFF + c);
    }
    __syncthreads();

    int f = tid & 127;
    for (int r = tid >> 7; r < 32; r += 2) {
        float acc = bsh[f];
        #pragma unroll
        for (int j = 0; j < LFF; j++) acc += lsh[r][j] * Wsh[j][f];
        if (LOGSIG) {
            acc = (acc >= 0.f) ? -__logf(1.f + __expf(-acc))
                               : acc - __logf(1.f + __expf(acc));
        }
        out[(size_t)(row0 + r) * FF + f] = acc;
    }
}

// ---------------- mask: any over HIST, dtype self-detection ----------------
__global__ void mask_kernel(const unsigned char* __restrict__ m)
{
    int tid = threadIdx.x;
    const unsigned int* w = (const unsigned int*)m;
    bool okI = true, okF = true;
    for (int j = tid; j < (HISTN * BB * LL) / 4; j += 256) {
        unsigned int x = w[j];
        if (x > 1u) okI = false;
        if (x != 0u && x != 0x3F800000u) okF = false;
    }
    okI = __syncthreads_and((int)okI) != 0;
    okF = __syncthreads_and((int)okF) != 0;
    int cls = okI ? 0 : (okF ? 1 : 2);

    for (int i = tid; i < BB * LL; i += 256) {
        unsigned int any = 0;
        #pragma unroll
        for (int h = 0; h < HISTN; h++) {
            int j = h * BB * LL + i;
            unsigned int v;
            if (cls == 0)      v = w[j];
            else if (cls == 1) v = (w[j] != 0u);
            else               v = m[j];
            any |= v;
        }
        g_mask[i] = any ? 1 : 0;
    }
}

// ---------------- 30720x128x128 GEMM (packed f32x2): C = A@W^T + bias (+E1-E2) ----------------
template<bool SUM_AB, bool EPI>
__global__ __launch_bounds__(256) void gemm128_kernel(
    const float* __restrict__ A1, const float* __restrict__ A2,
    const float* __restrict__ W,  const float* __restrict__ bias,
    float* __restrict__ C,
    const float* __restrict__ E1, const float* __restrict__ E2)
{
    __shared__ float Ash[64][36];
    __shared__ float Wsh[32][132];
    int tid = threadIdx.x;
    int tx = tid & 31, ty = tid >> 5;
    int m0 = blockIdx.x * 64;

    u64 acc2[8][2];
    #pragma unroll
    for (int i = 0; i < 8; i++) { acc2[i][0] = 0ull; acc2[i][1] = 0ull; }

    for (int k0 = 0; k0 < 128; k0 += 32) {
        #pragma unroll
        for (int i = 0; i < 2; i++) {
            int idx = tid + i * 256;
            int row = idx >> 3, c = (idx & 7) * 4;
            float4 a = *(const float4*)(A1 + (size_t)(m0 + row) * FF + k0 + c);
            if (SUM_AB) {
                float4 b = *(const float4*)(A2 + (size_t)(m0 + row) * FF + k0 + c);
                a.x += b.x; a.y += b.y; a.z += b.z; a.w += b.w;
            }
            *(float4*)&Ash[row][c] = a;
        }
        #pragma unroll
        for (int i = 0; i < 16; i++) {
            int idx = tid + i * 256;
            int n = idx >> 5, kk = idx & 31;
            Wsh[kk][n] = W[n * FF + k0 + kk];
        }
        __syncthreads();
        #pragma unroll
        for (int k = 0; k < 32; k++) {
            ulonglong2 b2 = *(ulonglong2*)&Wsh[k][tx * 4];
            #pragma unroll
            for (int i = 0; i < 8; i++) {
                float a = Ash[ty * 8 + i][k];
                u64 a2 = pk2(a, a);
                fma2(acc2[i][0], a2, b2.x);
                fma2(acc2[i][1], a2, b2.y);
            }
        }
        __syncthreads();
    }

    int n = tx * 4;
    float4 bb = *(const float4*)(bias + n);
    #pragma unroll
    for (int i = 0; i < 8; i++) {
        int m = m0 + ty * 8 + i;
        float2 lo = up2(acc2[i][0]), hi = up2(acc2[i][1]);
        float4 o;
        o.x = lo.x + bb.x; o.y = lo.y + bb.y;
        o.z = hi.x + bb.z; o.w = hi.y + bb.w;
        if (EPI) {
            float4 e1 = *(const float4*)(E1 + (size_t)m * FF + n);
            float4 e2 = *(const float4*)(E2 + (size_t)m * FF + n);
            o.x += e1.x - e2.x; o.y += e1.y - e2.y;
            o.z += e1.z - e2.z; o.w += e1.w - e2.w;
        }
        *(float4*)(C + (size_t)m * FF + n) = o;
    }
}

// ---------------- fused q+r GEMM (packed f32x2) ----------------
__global__ __launch_bounds__(256, 2) void gemm_qr_kernel(
    const float* __restrict__ A1, const float* __restrict__ A2,
    const float* __restrict__ Wq, const float* __restrict__ bq,
    const float* __restrict__ Wr, const float* __restrict__ br,
    float* __restrict__ Cq, float* __restrict__ Cr)
{
    __shared__ float Ash[64][36];
    __shared__ float W1[32][132];
    __shared__ float W2[32][132];
    int tid = threadIdx.x;
    int tx = tid & 31, ty = tid >> 5;
    int m0 = blockIdx.x * 64;

    u64 aq[8][2], ar[8][2];
    #pragma unroll
    for (int i = 0; i < 8; i++) {
        aq[i][0] = aq[i][1] = 0ull;
        ar[i][0] = ar[i][1] = 0ull;
    }

    for (int k0 = 0; k0 < 128; k0 += 32) {
        #pragma unroll
        for (int i = 0; i < 2; i++) {
            int idx = tid + i * 256;
            int row = idx >> 3, c = (idx & 7) * 4;
            float4 a = *(const float4*)(A1 + (size_t)(m0 + row) * FF + k0 + c);
            float4 b = *(const float4*)(A2 + (size_t)(m0 + row) * FF + k0 + c);
            a.x += b.x; a.y += b.y; a.z += b.z; a.w += b.w;
            *(float4*)&Ash[row][c] = a;
        }
        #pragma unroll
        for (int i = 0; i < 16; i++) {
            int idx = tid + i * 256;
            int n = idx >> 5, kk = idx & 31;
            W1[kk][n] = Wq[n * FF + k0 + kk];
            W2[kk][n] = Wr[n * FF + k0 + kk];
        }
        __syncthreads();
        #pragma unroll
        for (int k = 0; k < 32; k++) {
            ulonglong2 q2 = *(ulonglong2*)&W1[k][tx * 4];
            ulonglong2 r2 = *(ulonglong2*)&W2[k][tx * 4];
            #pragma unroll
            for (int i = 0; i < 8; i++) {
                float a = Ash[ty * 8 + i][k];
                u64 a2 = pk2(a, a);
                fma2(aq[i][0], a2, q2.x);
                fma2(aq[i][1], a2, q2.y);
                fma2(ar[i][0], a2, r2.x);
                fma2(ar[i][1], a2, r2.y);
            }
        }
        __syncthreads();
    }

    int n = tx * 4;
    float4 bq4 = *(const float4*)(bq + n);
    float4 br4 = *(const float4*)(br + n);
    #pragma unroll
    for (int i = 0; i < 8; i++) {
        int m = m0 + ty * 8 + i;
        float2 qlo = up2(aq[i][0]), qhi = up2(aq[i][1]);
        float2 rlo = up2(ar[i][0]), rhi = up2(ar[i][1]);
        float4 oq, orr;
        oq.x  = qlo.x + bq4.x; oq.y  = qlo.y + bq4.y;
        oq.z  = qhi.x + bq4.z; oq.w  = qhi.y + bq4.w;
        orr.x = rlo.x + br4.x; orr.y = rlo.y + br4.y;
        orr.z = rhi.x + br4.z; orr.w = rhi.y + br4.w;
        *(float4*)(Cq + (size_t)m * FF + n) = oq;
        *(float4*)(Cr + (size_t)m * FF + n) = orr;
    }
}

// ---------------- attention v2 + fast exp (ONLY change vs round-7 attn2) ----------------
#define TPB2 6
__global__ __launch_bounds__(256) void attn2_kernel()
{
    __shared__ float sc[32][260];       // scores -> unnormalized p (padded rows)
    __shared__ float lvsh[256][16];     // logsig(val) for this (b,h)
    __shared__ float qsh[32][16];
    __shared__ float sinv[32];
    __shared__ float pb[256][4];        // phase-B partials

    int tid = threadIdx.x;
    int b = blockIdx.x >> 3, h = blockIdx.x & 7;
    int t0 = blockIdx.y * TPB2;
    int l = tid;
    int warp = tid >> 5, lane = tid & 31;

    // K row for this l in registers
    float4 k0, k1, k2, k3;
    {
        const float* kp = g_Kproj + ((size_t)(b * LL + l)) * FF + h * DHH;
        k0 = *(const float4*)(kp);
        k1 = *(const float4*)(kp + 4);
        k2 = *(const float4*)(kp + 8);
        k3 = *(const float4*)(kp + 12);
        const float* lvp = g_LV + ((size_t)(b * LL + l)) * FF + h * DHH;
        #pragma unroll
        for (int i = 0; i < 4; i++)
            *(float4*)&lvsh[l][i * 4] = *(const float4*)(lvp + i * 4);
    }
    bool mon = g_mask[b * LL + l] != 0;

    // phase-B thread mapping
    int dq = tid & 3;            // d quad
    int half = (tid >> 2) & 1;   // l parity
    int vB = tid >> 3;           // v row 0..31

    for (int t = t0; t < t0 + TPB2; t++) {
        __syncthreads();                 // protect qsh/sc/sinv reuse
        if (tid < 128) {                 // load q tile [32,16] as float4
            int v = tid >> 2, q4 = tid & 3;
            *(float4*)&qsh[v][q4 * 4] =
                *(const float4*)(g_q + ((size_t)((t * BB + b) * VV + v)) * FF + h * DHH + q4 * 4);
        }
        __syncthreads();

        // ---- Phase A: scores, thread l computes column l for all 32 v ----
        #pragma unroll
        for (int v = 0; v < 32; v++) {
            float4 q0 = *(float4*)&qsh[v][0];
            float4 q1 = *(float4*)&qsh[v][4];
            float4 q2 = *(float4*)&qsh[v][8];
            float4 q3 = *(float4*)&qsh[v][12];
            float s = q0.x * k0.x + q0.y * k0.y + q0.z * k0.z + q0.w * k0.w
                    + q1.x * k1.x + q1.y * k1.y + q1.z * k1.z + q1.w * k1.w
                    + q2.x * k2.x + q2.y * k2.y + q2.z * k2.z + q2.w * k2.w
                    + q3.x * k3.x + q3.y * k3.y + q3.z * k3.z + q3.w * k3.w;
            sc[v][l] = mon ? (s * 0.25f) : -1e9f;
        }
        __syncthreads();

        // ---- softmax over l (rows = v): warp handles rows warp, warp+8, +16, +24 ----
        #pragma unroll
        for (int rr = 0; rr < 4; rr++) {
            int rv = warp + rr * 8;
            float4 a = *(float4*)&sc[rv][lane * 8];
            float4 c = *(float4*)&sc[rv][lane * 8 + 4];
            float mx = fmaxf(fmaxf(fmaxf(a.x, a.y), fmaxf(a.z, a.w)),
                             fmaxf(fmaxf(c.x, c.y), fmaxf(c.z, c.w)));
            #pragma unroll
            for (int o = 16; o > 0; o >>= 1)
                mx = fmaxf(mx, __shfl_xor_sync(0xffffffffu, mx, o));
            a.x = __expf(a.x - mx); a.y = __expf(a.y - mx);
            a.z = __expf(a.z - mx); a.w = __expf(a.w - mx);
            c.x = __expf(c.x - mx); c.y = __expf(c.y - mx);
            c.z = __expf(c.z - mx); c.w = __expf(c.w - mx);
            float sm = a.x + a.y + a.z + a.w + c.x + c.y + c.z + c.w;
            #pragma unroll
            for (int o = 16; o > 0; o >>= 1)
                sm += __shfl_xor_sync(0xffffffffu, sm, o);
            *(float4*)&sc[rv][lane * 8] = a;
            *(float4*)&sc[rv][lane * 8 + 4] = c;
            if (lane == 0) sinv[rv] = __fdividef(1.f, sm);
        }
        __syncthreads();

        // ---- Phase B: acc[d4] = sum over half the l's of p * lv ----
        {
            float4 acc = make_float4(0.f, 0.f, 0.f, 0.f);
            #pragma unroll 4
            for (int j = 0; j < 128; j++) {
                int ll2 = 2 * j + half;
                float p = sc[vB][ll2];
                float4 lv = *(float4*)&lvsh[ll2][dq * 4];
                acc.x += p * lv.x; acc.y += p * lv.y;
                acc.z += p * lv.z; acc.w += p * lv.w;
            }
            *(float4*)&pb[tid][0] = acc;
            __syncthreads();
            if (half == 0) {
                float4 o = *(float4*)&pb[tid ^ 4][0];
                o.x += acc.x; o.y += acc.y; o.z += acc.z; o.w += acc.w;
                float si = sinv[vB];
                float4 r4 = *(const float4*)(g_r + ((size_t)((t * BB + b) * VV + vB)) * FF + h * DHH + dq * 4);
                float4 res;
                res.x = r4.x * __expf(o.x * si);
                res.y = r4.y * __expf(o.y * si);
                res.z = r4.z * __expf(o.z * si);
                res.w = r4.w * __expf(o.w * si);
                *(float4*)(g_pre + ((size_t)(t * BB + b)) * (VV * FF)
                           + h * (VV * DHH) + vB * DHH + dq * 4) = res;
            }
        }
    }
}

// ---------------- launch ----------------
extern "C" void kernel_launch(void* const* d_in, const int* in_sizes, int n_in,
                              void* d_out, int out_size)
{
    const float* vehicles    = (const float*)d_in[0];
    const float* initial_pos = (const float*)d_in[1];
    const float* lanes       = (const float*)d_in[2];
    const unsigned char* mask_lanes = (const unsigned char*)d_in[3];
    const float* Wk = (const float*)d_in[4];
    const float* bk = (const float*)d_in[5];
    const float* Wv = (const float*)d_in[6];
    const float* bv = (const float*)d_in[7];
    const float* Wq = (const float*)d_in[8];
    const float* bq = (const float*)d_in[9];
    const float* Wr = (const float*)d_in[10];
    const float* br = (const float*)d_in[11];
    const float* Wc = (const float*)d_in[12];
    const float* bc = (const float*)d_in[13];
    float* out = (float*)d_out;

    float *gK, *gLV, *gq, *gr, *gpre;
    cudaGetSymbolAddress((void**)&gK,   g_Kproj);
    cudaGetSymbolAddress((void**)&gLV,  g_LV);
    cudaGetSymbolAddress((void**)&gq,   g_q);
    cudaGetSymbolAddress((void**)&gr,   g_r);
    cudaGetSymbolAddress((void**)&gpre, g_pre);

    // 1) lane projections + mask
    lane_proj_kernel<false><<<BB * LL / 32, 256>>>(lanes, Wk, bk, gK);
    lane_proj_kernel<true ><<<BB * LL / 32, 256>>>(lanes, Wv, bv, gLV);
    mask_kernel<<<1, 256>>>(mask_lanes);

    // 2) fused q, r projections on v = vehicles + initial_pos
    gemm_qr_kernel<<<MROWS / 64, 256>>>(vehicles, initial_pos, Wq, bq, Wr, br, gq, gr);

    // 3) attention
    attn2_kernel<<<dim3(BB * HH, TT / TPB2), 256>>>();

    // 4) combine + residual: out = pre @ Wc^T + bc + vehicles - initial_pos
    gemm128_kernel<false, true><<<MROWS / 64, 256>>>(gpre, nullptr, Wc, bc, out, vehicles, initial_pos);
}